// round 3
// baseline (speedup 1.0000x reference)
#include <cuda_runtime.h>
#include <cuda_bf16.h>

// VisualRetina: strided 32x32 subsample -> Morton order -> cubic LSQ fit per
// 16-elem chunk -> [c0,c1,c2,c3,sigma] averaged over 3 channels.
// Input : x (256,3,224,224) f32
// Output: (256,64,1,5) f32
//
// Closed-form pinv of T=[t^3,t^2,t,1], t=linspace(-1,1,16). Odd moments vanish:
//   c0 = (S2*b0 - S4*b2)/D1,  c2 = (S6*b2 - S4*b0)/D1,  D1 = S6*S2 - S4^2
//   c1 = (S0*b1 - S2*b3)/D2,  c3 = (S4*b3 - S2*b1)/D2,  D2 = S4*S0 - S2^2
// with bk = sum_t t^(3-k)... (b0=sum t^3 v, b1=sum t^2 v, b2=sum t v, b3=sum v)

namespace {
// exact rational moments of t_i = (2i-15)/15, i=0..15
constexpr double S0 = 16.0;
constexpr double S2 = 1360.0 / 225.0;          // sum t^2
constexpr double S4 = 206992.0 / 50625.0;      // sum t^4
constexpr double S6 = 37308880.0 / 11390625.0; // sum t^6
constexpr double D1 = S6 * S2 - S4 * S4;
constexpr double D2 = S4 * S0 - S2 * S2;

constexpr float P00 = (float)(S2 / D1);
constexpr float P01 = (float)(S4 / D1);
constexpr float P20 = (float)(S6 / D1);
constexpr float P10 = (float)(S0 / D2);
constexpr float P11 = (float)(S2 / D2);
constexpr float P30 = (float)(S4 / D2);
} // namespace

__device__ __forceinline__ void fit_accum(const float v[16], float acc[5]) {
    float b0 = 0.f, b1 = 0.f, b2 = 0.f, b3 = 0.f;
#pragma unroll
    for (int t = 0; t < 16; ++t) {
        const float u  = -1.0f + (float)t * (2.0f / 15.0f);
        const float u2 = u * u;
        b3 += v[t];
        b2 = fmaf(u,      v[t], b2);
        b1 = fmaf(u2,     v[t], b1);
        b0 = fmaf(u2 * u, v[t], b0);
    }
    const float c0 = fmaf(P00, b0, -P01 * b2);
    const float c2 = fmaf(P20, b2, -P01 * b0);
    const float c1 = fmaf(P10, b1, -P11 * b3);
    const float c3 = fmaf(P30, b3, -P11 * b1);

    float sse = 0.f;
#pragma unroll
    for (int t = 0; t < 16; ++t) {
        const float u = -1.0f + (float)t * (2.0f / 15.0f);
        const float pred = fmaf(fmaf(fmaf(c0, u, c1), u, c2), u, c3);
        const float d = v[t] - pred;
        sse = fmaf(d, d, sse);
    }
    acc[0] += c0;
    acc[1] += c1;
    acc[2] += c2;
    acc[3] += c3;
    acc[4] += sqrtf(sse * (1.0f / 16.0f));
}

__global__ __launch_bounds__(128) void retina_kernel(const float* __restrict__ x,
                                                     float* __restrict__ out) {
    const int tid = blockIdx.x * blockDim.x + threadIdx.x;
    if (tid >= 256 * 64) return;
    const int b = tid >> 6;   // batch
    const int n = tid & 63;   // chunk = upper 6 Morton bits

    // Morton upper-bit decode (x even bits, y odd bits of n)
    const int xn = (n & 1) | ((n >> 1) & 2) | ((n >> 2) & 4);
    const int yn = ((n >> 1) & 1) | ((n >> 2) & 2) | ((n >> 3) & 4);

    const float* p0 = x + (size_t)b * (3 * 224 * 224) + (size_t)(28 * yn) * 224 + 28 * xn;
    const float* p1 = p0 + 224 * 224;
    const float* p2 = p0 + 2 * 224 * 224;

    float v0[16], v1[16], v2[16];
#pragma unroll
    for (int t = 0; t < 16; ++t) {
        // Morton low-bit decode (compile-time after unroll)
        const int xt = (t & 1) | ((t >> 1) & 2);
        const int yt = ((t >> 1) & 1) | ((t >> 2) & 2);
        const int off = 7 * yt * 224 + 7 * xt;
        v0[t] = __ldg(p0 + off);
        v1[t] = __ldg(p1 + off);
        v2[t] = __ldg(p2 + off);
    }

    float acc[5] = {0.f, 0.f, 0.f, 0.f, 0.f};
    fit_accum(v0, acc);
    fit_accum(v1, acc);
    fit_accum(v2, acc);

    float* o = out + (size_t)tid * 5;
#pragma unroll
    for (int k = 0; k < 5; ++k) o[k] = acc[k] * (1.0f / 3.0f);
}

extern "C" void kernel_launch(void* const* d_in, const int* in_sizes, int n_in,
                              void* d_out, int out_size) {
    const float* x = (const float*)d_in[0];
    float* out = (float*)d_out;
    retina_kernel<<<128, 128>>>(x, out);
}